// round 10
// baseline (speedup 1.0000x reference)
#include <cuda_runtime.h>

// IoU distance: out[i][j] = inter/union + 1e-16
//   inter = min(lw_i, rw_j) * min(lh_i, rh_j)
//   union = lw_i*lh_i + rw_j*rh_j - inter
//
// lhs: [N,2] fp32 (N = 100000), rhs: [512,2] fp32, out: [N,512] fp32.
//
// R10: store policy = write-through (st.global.wt). R6-R9 A/B showed
// evict-first (__stcs) beats write-back on harness wall time: write-back
// leaves ~60MB dirty in L2 whose drain lands on the NEXT graph replay
// (invisible to ncu -c 1). Write-through is the endpoint of that mechanism:
// zero dirty output state, clean replay steady-state. Warp stores are full
// 512B-contiguous line groups, so no partial-line penalty.
// Kept (validated): chunk=16 / 6250 blocks, 2-row pipelined ILP,
// register-resident rhs, rcp.approx + FFMA(+EPS), launch_bounds(128,10).

#ifndef EPS_IOU
#define EPS_IOU 1e-16f
#endif

#define ROWS_PER_IT 2

__device__ __forceinline__ float rcp_approx(float x) {
    float r;
    asm("rcp.approx.ftz.f32 %0, %1;" : "=f"(r) : "f"(x));
    return r;
}

__device__ __forceinline__ void stg_wt_128(float4* p, float4 v) {
    asm volatile("st.global.wt.v4.f32 [%0], {%1, %2, %3, %4};"
                 :: "l"(p), "f"(v.x), "f"(v.y), "f"(v.z), "f"(v.w)
                 : "memory");
}

__global__ __launch_bounds__(128, 10)
void iou_distance_kernel(const float2* __restrict__ lhs,
                         const float4* __restrict__ rhs4,
                         float4* __restrict__ out4,
                         int chunk,              // rows per block (multiple of ROWS_PER_IT)
                         int n_rows)
{
    const int t = threadIdx.x;               // 0..127 -> columns 4t..4t+3

    // This thread's 4 rhs boxes, register-resident for the whole kernel.
    float rw[4], rh[4], ra[4];
    {
        float4 p0 = rhs4[2 * t + 0];
        float4 p1 = rhs4[2 * t + 1];
        rw[0] = p0.x; rh[0] = p0.y;
        rw[1] = p0.z; rh[1] = p0.w;
        rw[2] = p1.x; rh[2] = p1.y;
        rw[3] = p1.z; rh[3] = p1.w;
#pragma unroll
        for (int k = 0; k < 4; ++k) ra[k] = rw[k] * rh[k];
    }

    int row0 = blockIdx.x * chunk;
    if (row0 >= n_rows) return;
    int row_end = row0 + chunk;
    if (row_end > n_rows) row_end = n_rows;
    const int n_it = (row_end - row0) / ROWS_PER_IT;

    const float2* lp = lhs + row0;
    float4*       op = out4 + (long long)row0 * 128 + t;

    // Prologue: prefetch first ROWS_PER_IT rows.
    float2 lcur[ROWS_PER_IT];
#pragma unroll
    for (int r = 0; r < ROWS_PER_IT; ++r) lcur[r] = lp[r];
    lp += ROWS_PER_IT;

    for (int it = 0; it < n_it; ++it) {
        // Prefetch next iteration's rows before computing on lcur.
        float2 lnext[ROWS_PER_IT];
        if (it + 1 < n_it) {
#pragma unroll
            for (int r = 0; r < ROWS_PER_IT; ++r) lnext[r] = lp[r];
            lp += ROWS_PER_IT;
        }

#pragma unroll
        for (int r = 0; r < ROWS_PER_IT; ++r) {
            const float lw = lcur[r].x, lh = lcur[r].y;
            const float la = lw * lh;

            float o[4];
#pragma unroll
            for (int k = 0; k < 4; ++k) {
                const float iw    = fminf(lw, rw[k]);
                const float ih    = fminf(lh, rh[k]);
                const float inter = iw * ih;                  // FMUL
                const float uni   = (la + ra[k]) - inter;     // FADD, FADD
                o[k] = fmaf(inter, rcp_approx(uni), EPS_IOU); // MUFU + FFMA
            }

            float4 v;
            v.x = o[0]; v.y = o[1]; v.z = o[2]; v.w = o[3];
            stg_wt_128(op + (long long)r * 128, v);   // write-through STG.128
        }
        op += (long long)ROWS_PER_IT * 128;

#pragma unroll
        for (int r = 0; r < ROWS_PER_IT; ++r) lcur[r] = lnext[r];
    }
}

extern "C" void kernel_launch(void* const* d_in, const int* in_sizes, int n_in,
                              void* d_out, int out_size)
{
    const float2* lhs  = (const float2*)d_in[0];
    const float4* rhs4 = (const float4*)d_in[1];
    float4*       out4 = (float4*)d_out;

    const int n_rows = in_sizes[0] / 2;      // 100000

    // 16-row chunks -> 6250 blocks, no tail (100000 = 6250 * 16).
    int chunk = 16;
    int grid  = (n_rows + chunk - 1) / chunk;

    iou_distance_kernel<<<grid, 128>>>(lhs, rhs4, out4, chunk, n_rows);
}

// round 11
// speedup vs baseline: 1.0430x; 1.0430x over previous
#include <cuda_runtime.h>

// IoU distance: out[i][j] = inter/union + 1e-16
//   inter = min(lw_i, rw_j) * min(lh_i, rh_j)
//   union = lw_i*lh_i + rw_j*rh_j - inter
//
// lhs: [N,2] fp32 (N = 100000), rhs: [512,2] fp32, out: [N,512] fp32.
//
// FINAL (= R7 config, best of 9 measured variants at 33.5us wall, twice):
//  - thread t owns columns 4t..4t+3; rhs register-resident, areas precomputed
//  - 2-row software-pipelined ILP (prefetch next rows before compute)
//  - rcp.approx.ftz + single FFMA folding +EPS (rel_err ~8e-8)
//  - __stcs evict-first STG.128: A/B-tested vs write-back (34.3-34.9us) and
//    write-through (34.9us) -- evict-first reproducibly best on replay wall
//    time despite equal ncu single-launch time
//  - chunk=16 rows -> 6250 blocks, exact division, best grid granularity
//    (chunk 8 = more launch overhead; chunk 88 single-wave = tail imbalance)
//  - launch_bounds(128,10): 47 regs, 10 blocks/SM, no spills

#ifndef EPS_IOU
#define EPS_IOU 1e-16f
#endif

#define ROWS_PER_IT 2

__device__ __forceinline__ float rcp_approx(float x) {
    float r;
    asm("rcp.approx.ftz.f32 %0, %1;" : "=f"(r) : "f"(x));
    return r;
}

__global__ __launch_bounds__(128, 10)
void iou_distance_kernel(const float2* __restrict__ lhs,
                         const float4* __restrict__ rhs4,
                         float4* __restrict__ out4,
                         int chunk,              // rows per block (multiple of ROWS_PER_IT)
                         int n_rows)
{
    const int t = threadIdx.x;               // 0..127 -> columns 4t..4t+3

    // This thread's 4 rhs boxes, register-resident for the whole kernel.
    float rw[4], rh[4], ra[4];
    {
        float4 p0 = rhs4[2 * t + 0];
        float4 p1 = rhs4[2 * t + 1];
        rw[0] = p0.x; rh[0] = p0.y;
        rw[1] = p0.z; rh[1] = p0.w;
        rw[2] = p1.x; rh[2] = p1.y;
        rw[3] = p1.z; rh[3] = p1.w;
#pragma unroll
        for (int k = 0; k < 4; ++k) ra[k] = rw[k] * rh[k];
    }

    int row0 = blockIdx.x * chunk;
    if (row0 >= n_rows) return;
    int row_end = row0 + chunk;
    if (row_end > n_rows) row_end = n_rows;
    const int n_it = (row_end - row0) / ROWS_PER_IT;

    const float2* lp = lhs + row0;
    float4*       op = out4 + (long long)row0 * 128 + t;

    // Prologue: prefetch first ROWS_PER_IT rows.
    float2 lcur[ROWS_PER_IT];
#pragma unroll
    for (int r = 0; r < ROWS_PER_IT; ++r) lcur[r] = lp[r];
    lp += ROWS_PER_IT;

    for (int it = 0; it < n_it; ++it) {
        // Prefetch next iteration's rows before computing on lcur.
        float2 lnext[ROWS_PER_IT];
        if (it + 1 < n_it) {
#pragma unroll
            for (int r = 0; r < ROWS_PER_IT; ++r) lnext[r] = lp[r];
            lp += ROWS_PER_IT;
        }

#pragma unroll
        for (int r = 0; r < ROWS_PER_IT; ++r) {
            const float lw = lcur[r].x, lh = lcur[r].y;
            const float la = lw * lh;

            float o[4];
#pragma unroll
            for (int k = 0; k < 4; ++k) {
                const float iw    = fminf(lw, rw[k]);
                const float ih    = fminf(lh, rh[k]);
                const float inter = iw * ih;                  // FMUL
                const float uni   = (la + ra[k]) - inter;     // FADD, FADD
                o[k] = fmaf(inter, rcp_approx(uni), EPS_IOU); // MUFU + FFMA
            }

            float4 v;
            v.x = o[0]; v.y = o[1]; v.z = o[2]; v.w = o[3];
            __stcs(op + (long long)r * 128, v);   // evict-first streaming STG.128
        }
        op += (long long)ROWS_PER_IT * 128;

#pragma unroll
        for (int r = 0; r < ROWS_PER_IT; ++r) lcur[r] = lnext[r];
    }
}

extern "C" void kernel_launch(void* const* d_in, const int* in_sizes, int n_in,
                              void* d_out, int out_size)
{
    const float2* lhs  = (const float2*)d_in[0];
    const float4* rhs4 = (const float4*)d_in[1];
    float4*       out4 = (float4*)d_out;

    const int n_rows = in_sizes[0] / 2;      // 100000

    // 16-row chunks -> 6250 blocks, no tail (100000 = 6250 * 16).
    int chunk = 16;
    int grid  = (n_rows + chunk - 1) / chunk;

    iou_distance_kernel<<<grid, 128>>>(lhs, rhs4, out4, chunk, n_rows);
}

// round 12
// speedup vs baseline: 1.0592x; 1.0155x over previous
#include <cuda_runtime.h>

// IoU distance: out[i][j] = inter/union + 1e-16
//   inter = min(lw_i, rw_j) * min(lh_i, rh_j)
//   union = lw_i*lh_i + rw_j*rh_j - inter
//
// lhs: [N,2] fp32 (N = 100000), rhs: [512,2] fp32, out: [N,512] fp32.
//
// FINAL — best of 10 measured variants; 33.47-33.50us wall, reproduced 3x.
//  - thread t owns columns 4t..4t+3; rhs register-resident, areas precomputed
//  - 2-row software-pipelined ILP (prefetch next rows before compute)
//  - rcp.approx.ftz + single FFMA folding +EPS (rel_err ~8e-8)
//  - __stcs evict-first STG.128: A/B-tested vs write-back (34.3-34.9us) and
//    write-through (34.9us); evict-first reproducibly best on replay wall time
//  - chunk=16 rows -> 6250 blocks, exact division, best grid granularity
//  - launch_bounds(128,10): 47 regs, 10 blocks/SM, no spills
// Kernel-internal time invariant at ~31.5us across all structural variants
// (L1/LTS/latency equilibrium); this config minimizes the wall-clock residual.

#ifndef EPS_IOU
#define EPS_IOU 1e-16f
#endif

#define ROWS_PER_IT 2

__device__ __forceinline__ float rcp_approx(float x) {
    float r;
    asm("rcp.approx.ftz.f32 %0, %1;" : "=f"(r) : "f"(x));
    return r;
}

__global__ __launch_bounds__(128, 10)
void iou_distance_kernel(const float2* __restrict__ lhs,
                         const float4* __restrict__ rhs4,
                         float4* __restrict__ out4,
                         int chunk,              // rows per block (multiple of ROWS_PER_IT)
                         int n_rows)
{
    const int t = threadIdx.x;               // 0..127 -> columns 4t..4t+3

    // This thread's 4 rhs boxes, register-resident for the whole kernel.
    float rw[4], rh[4], ra[4];
    {
        float4 p0 = rhs4[2 * t + 0];
        float4 p1 = rhs4[2 * t + 1];
        rw[0] = p0.x; rh[0] = p0.y;
        rw[1] = p0.z; rh[1] = p0.w;
        rw[2] = p1.x; rh[2] = p1.y;
        rw[3] = p1.z; rh[3] = p1.w;
#pragma unroll
        for (int k = 0; k < 4; ++k) ra[k] = rw[k] * rh[k];
    }

    int row0 = blockIdx.x * chunk;
    if (row0 >= n_rows) return;
    int row_end = row0 + chunk;
    if (row_end > n_rows) row_end = n_rows;
    const int n_it = (row_end - row0) / ROWS_PER_IT;

    const float2* lp = lhs + row0;
    float4*       op = out4 + (long long)row0 * 128 + t;

    // Prologue: prefetch first ROWS_PER_IT rows.
    float2 lcur[ROWS_PER_IT];
#pragma unroll
    for (int r = 0; r < ROWS_PER_IT; ++r) lcur[r] = lp[r];
    lp += ROWS_PER_IT;

    for (int it = 0; it < n_it; ++it) {
        // Prefetch next iteration's rows before computing on lcur.
        float2 lnext[ROWS_PER_IT];
        if (it + 1 < n_it) {
#pragma unroll
            for (int r = 0; r < ROWS_PER_IT; ++r) lnext[r] = lp[r];
            lp += ROWS_PER_IT;
        }

#pragma unroll
        for (int r = 0; r < ROWS_PER_IT; ++r) {
            const float lw = lcur[r].x, lh = lcur[r].y;
            const float la = lw * lh;

            float o[4];
#pragma unroll
            for (int k = 0; k < 4; ++k) {
                const float iw    = fminf(lw, rw[k]);
                const float ih    = fminf(lh, rh[k]);
                const float inter = iw * ih;                  // FMUL
                const float uni   = (la + ra[k]) - inter;     // FADD, FADD
                o[k] = fmaf(inter, rcp_approx(uni), EPS_IOU); // MUFU + FFMA
            }

            float4 v;
            v.x = o[0]; v.y = o[1]; v.z = o[2]; v.w = o[3];
            __stcs(op + (long long)r * 128, v);   // evict-first streaming STG.128
        }
        op += (long long)ROWS_PER_IT * 128;

#pragma unroll
        for (int r = 0; r < ROWS_PER_IT; ++r) lcur[r] = lnext[r];
    }
}

extern "C" void kernel_launch(void* const* d_in, const int* in_sizes, int n_in,
                              void* d_out, int out_size)
{
    const float2* lhs  = (const float2*)d_in[0];
    const float4* rhs4 = (const float4*)d_in[1];
    float4*       out4 = (float4*)d_out;

    const int n_rows = in_sizes[0] / 2;      // 100000

    // 16-row chunks -> 6250 blocks, no tail (100000 = 6250 * 16).
    int chunk = 16;
    int grid  = (n_rows + chunk - 1) / chunk;

    iou_distance_kernel<<<grid, 128>>>(lhs, rhs4, out4, chunk, n_rows);
}